// round 2
// baseline (speedup 1.0000x reference)
#include <cuda_runtime.h>
#include <cfloat>

#define P_PTS    32
#define C_OUT_N  64
#define NACC     54
#define BN_EPS   1e-3

typedef unsigned long long ull;

// Global scratch (54 moment accumulators, 128 BN affine params)
__device__ float g_acc[NACC];
__device__ float g_st[2 * C_OUT_N];   // s[64], t[64]

// ---------------- f32x2 helpers (sm_100+) ----------------
__device__ __forceinline__ ull pack2(float lo, float hi) {
    ull r;
    asm("mov.b64 %0, {%1, %2};" : "=l"(r) : "f"(lo), "f"(hi));
    return r;
}
__device__ __forceinline__ void unpack2(ull v, float& lo, float& hi) {
    asm("mov.b64 {%0, %1}, %2;" : "=f"(lo), "=f"(hi) : "l"(v));
}
__device__ __forceinline__ ull ffma2(ull a, ull b, ull c) {
    ull d;
    asm("fma.rn.f32x2 %0, %1, %2, %3;" : "=l"(d) : "l"(a), "l"(b), "l"(c));
    return d;
}
__device__ __forceinline__ ull fmul2(ull a, ull b) {
    ull d;
    asm("mul.rn.f32x2 %0, %1, %2;" : "=l"(d) : "l"(a), "l"(b));
    return d;
}

// ---------------- kernel 0: zero the accumulators ----------------
__global__ void k_zero() {
    if (threadIdx.x < NACC) g_acc[threadIdx.x] = 0.0f;
}

// ---------------- kernel 1: global moment sums ----------------
// One thread per pillar; thread-local accumulate, warp bfly reduce, lane-0 atomics.
// NOTE (reference quirk): points_mean sums ALL P slots (incl. garbage padding)
// then divides by npts. So u_xyz = (sum over all 32 points of xyz) / npts,
// while everything feature-side (sv, G1, G2's sv factor) is over VALID points.
// Accumulator layout:
//   [0..3]   Sv    (sum of v over VALID points, 4 comps)
//   [4..5]   sum npts*cx, sum npts*cy
//   [6..15]  G1 sym 4x4 over valid pts: xx,xy,xz,xw, yy,yz,yw, zz,zw, ww
//   [16..35] G2[a][k] = sum_n sv_a * u_k   (a=0..3, k=0..4), u=(mx,my,mz,cx,cy)
//   [36..50] G3 sym 5x5: sum_n npts * u_j * u_k, (j<=k)
//   [51..53] Sa_xyz (sum of xyz over ALL P slots)  [= sum_n npts*u_xyz]
__global__ void __launch_bounds__(256) k_stats(const float4* __restrict__ vox,
                                               const int* __restrict__ npp,
                                               const float2* __restrict__ cen,
                                               int N)
{
    int n = blockIdx.x * blockDim.x + threadIdx.x;
    bool active = (n < N);
    int npts = 0;
    float cx = 0.f, cy = 0.f;
    if (active) {
        npts = npp[n];
        float2 c = cen[n];
        cx = c.x; cy = c.y;
    }

    float sv[4] = {0.f, 0.f, 0.f, 0.f};     // valid-point sums
    float sa[3] = {0.f, 0.f, 0.f};          // all-slot xyz sums
    float g1[10];
#pragma unroll
    for (int i = 0; i < 10; i++) g1[i] = 0.f;

    const float4* base = vox + (size_t)n * P_PTS;
    int pmax = active ? P_PTS : 0;
    for (int p = 0; p < pmax; p++) {
        float4 v = base[p];
        sa[0] += v.x; sa[1] += v.y; sa[2] += v.z;
        if (p < npts) {
            sv[0] += v.x; sv[1] += v.y; sv[2] += v.z; sv[3] += v.w;
            g1[0] += v.x * v.x; g1[1] += v.x * v.y; g1[2] += v.x * v.z; g1[3] += v.x * v.w;
            g1[4] += v.y * v.y; g1[5] += v.y * v.z; g1[6] += v.y * v.w;
            g1[7] += v.z * v.z; g1[8] += v.z * v.w;
            g1[9] += v.w * v.w;
        }
    }

    float fn  = (float)npts;
    float inv = (npts > 0) ? (1.0f / fn) : 0.0f;
    // u from ALL-slot mean (reference quirk)
    float u[5] = {sa[0] * inv, sa[1] * inv, sa[2] * inv, cx, cy};

    float acc[NACC];
    acc[0] = sv[0]; acc[1] = sv[1]; acc[2] = sv[2]; acc[3] = sv[3];
    acc[4] = fn * cx; acc[5] = fn * cy;
#pragma unroll
    for (int i = 0; i < 10; i++) acc[6 + i] = g1[i];
    {
        int idx = 16;
#pragma unroll
        for (int a = 0; a < 4; a++)
#pragma unroll
            for (int k = 0; k < 5; k++) acc[idx++] = sv[a] * u[k];
#pragma unroll
        for (int j = 0; j < 5; j++)
#pragma unroll
            for (int k = j; k < 5; k++) acc[idx++] = fn * u[j] * u[k];
    }
    acc[51] = sa[0]; acc[52] = sa[1]; acc[53] = sa[2];

    // warp butterfly reduce each accumulator
#pragma unroll
    for (int i = 0; i < NACC; i++) {
#pragma unroll
        for (int off = 16; off; off >>= 1)
            acc[i] += __shfl_xor_sync(0xffffffffu, acc[i], off);
    }
    if ((threadIdx.x & 31) == 0) {
#pragma unroll
        for (int i = 0; i < NACC; i++) atomicAdd(&g_acc[i], acc[i]);
    }
}

// ---------------- kernel 2: solve BN affine per channel ----------------
__global__ void k_bn(const float* __restrict__ W,
                     const float* __restrict__ gamma,
                     const float* __restrict__ beta,
                     int N)
{
    int o = threadIdx.x;
    if (o >= C_OUT_N) return;

    double A[NACC];
    for (int i = 0; i < NACC; i++) A[i] = (double)g_acc[i];

    const float* w = W + o * 9;
    double w0 = w[0], w1 = w[1], w2 = w[2], w3 = w[3], w4 = w[4];
    double w5 = w[5], w6 = w[6], w7 = w[7], w8 = w[8];

    double Wp[4] = {w0 + w4 + w7, w1 + w5 + w8, w2 + w6, w3};
    double Wt[5] = {w4, w5, w6, w7, w8};

    double NP = (double)N * (double)P_PTS;

    // mean: sum_valid x = Wp.Sv - Wt.(sum_n npts*u)
    //   sum npts*u_xyz = Sa (A[51..53]); sum npts*c = A[4..5]
    double sumx = Wp[0] * A[0] + Wp[1] * A[1] + Wp[2] * A[2] + Wp[3] * A[3]
                - (Wt[0] * A[51] + Wt[1] * A[52] + Wt[2] * A[53]
                   + Wt[3] * A[4] + Wt[4] * A[5]);
    double mean = sumx / NP;

    // q1 = Wp G1 Wp^T
    const double* G1 = &A[6];
    double q1 = Wp[0] * Wp[0] * G1[0] + 2.0 * Wp[0] * Wp[1] * G1[1]
              + 2.0 * Wp[0] * Wp[2] * G1[2] + 2.0 * Wp[0] * Wp[3] * G1[3]
              + Wp[1] * Wp[1] * G1[4] + 2.0 * Wp[1] * Wp[2] * G1[5]
              + 2.0 * Wp[1] * Wp[3] * G1[6]
              + Wp[2] * Wp[2] * G1[7] + 2.0 * Wp[2] * Wp[3] * G1[8]
              + Wp[3] * Wp[3] * G1[9];

    // q2 = -2 Wp G2 Wt^T
    double q2 = 0.0;
    for (int a = 0; a < 4; a++)
        for (int k = 0; k < 5; k++)
            q2 += Wp[a] * A[16 + a * 5 + k] * Wt[k];
    q2 *= -2.0;

    // q3 = Wt G3 Wt^T (symmetric triangular storage)
    double q3 = 0.0;
    {
        int idx = 36;
        for (int j = 0; j < 5; j++)
            for (int k = j; k < 5; k++) {
                double f = (j == k) ? 1.0 : 2.0;
                q3 += f * Wt[j] * Wt[k] * A[idx++];
            }
    }

    double E2  = (q1 + q2 + q3) / NP;
    double var = E2 - mean * mean;
    double s   = (double)gamma[o] * rsqrt(var + BN_EPS);
    double t   = (double)beta[o] - mean * s;

    g_st[o]           = (float)s;
    g_st[C_OUT_N + o] = (float)t;
}

// ---------------- kernel 3: folded GEMM + max/min + BN + relu ----------------
// One warp per pillar (grid-stride). Lane l owns channels {2l, 2l+1} via f32x2.
__global__ void __launch_bounds__(256) k_main(const float4* __restrict__ vox,
                                              const int* __restrict__ npp,
                                              const float2* __restrict__ cen,
                                              const float* __restrict__ W,
                                              float* __restrict__ out,
                                              int N)
{
    __shared__ ull sdup[8][P_PTS * 4];   // per-warp: 32 points x 4 duplicated comps

    int w    = threadIdx.x >> 5;
    int lane = threadIdx.x & 31;
    int warpsTotal = gridDim.x * 8;

    // fold weights once per warp (constant across pillars)
    int o0 = lane * 2;
    const float* wr0 = W + o0 * 9;
    const float* wr1 = W + o0 * 9 + 9;
    float a04 = wr0[4], a05 = wr0[5], a06 = wr0[6], a07 = wr0[7], a08 = wr0[8];
    float a14 = wr1[4], a15 = wr1[5], a16 = wr1[6], a17 = wr1[7], a18 = wr1[8];
    ull wp0 = pack2(wr0[0] + a04 + a07, wr1[0] + a14 + a17);
    ull wp1 = pack2(wr0[1] + a05 + a08, wr1[1] + a15 + a18);
    ull wp2 = pack2(wr0[2] + a06,       wr1[2] + a16);
    ull wp3 = pack2(wr0[3],             wr1[3]);

    float s0 = g_st[o0],           s1 = g_st[o0 + 1];
    float t0 = g_st[C_OUT_N + o0], t1 = g_st[C_OUT_N + o0 + 1];

    for (int n = blockIdx.x * 8 + w; n < N; n += warpsTotal) {
        int   npts = npp[n];
        float2 c   = cen[n];
        float4 v   = vox[(size_t)n * P_PTS + lane];

        // pillar "mean": sum over ALL 32 slots (reference quirk), divided by npts
        float sx = v.x, sy = v.y, sz = v.z;
#pragma unroll
        for (int off = 16; off; off >>= 1) {
            sx += __shfl_xor_sync(0xffffffffu, sx, off);
            sy += __shfl_xor_sync(0xffffffffu, sy, off);
            sz += __shfl_xor_sync(0xffffffffu, sz, off);
        }
        float inv = 1.0f / (float)npts;
        float mx = sx * inv, my = sy * inv, mz = sz * inv;

        // stage this warp's pillar, duplicated for f32x2 broadcast
        __syncwarp();
        ull* sp = &sdup[w][lane * 4];
        sp[0] = pack2(v.x, v.x);
        sp[1] = pack2(v.y, v.y);
        sp[2] = pack2(v.z, v.z);
        sp[3] = pack2(v.w, v.w);
        __syncwarp();

        // per-pillar bias for this lane's two channels
        float b0 = -(a04 * mx + a05 * my + a06 * mz + a07 * c.x + a08 * c.y);
        float b1 = -(a14 * mx + a15 * my + a16 * mz + a17 * c.x + a18 * c.y);

        float max0 = -FLT_MAX, max1 = -FLT_MAX;
        float min0 =  FLT_MAX, min1 =  FLT_MAX;

        const ulonglong2* sq = (const ulonglong2*)&sdup[w][0];
#pragma unroll 4
        for (int p = 0; p < npts; p++) {
            ulonglong2 q01 = sq[p * 2];
            ulonglong2 q23 = sq[p * 2 + 1];
            ull x = ffma2(q01.x, wp0,
                    ffma2(q01.y, wp1,
                    ffma2(q23.x, wp2,
                    fmul2(q23.y, wp3))));
            float x0, x1;
            unpack2(x, x0, x1);
            max0 = fmaxf(max0, x0); max1 = fmaxf(max1, x1);
            min0 = fminf(min0, x0); min1 = fminf(min1, x1);
        }

        float X0max = max0 + b0, X1max = max1 + b1;
        float X0min = min0 + b0, X1min = min1 + b1;
        if (npts < P_PTS) {                 // padded slots contribute x = 0
            X0max = fmaxf(X0max, 0.f); X1max = fmaxf(X1max, 0.f);
            X0min = fminf(X0min, 0.f); X1min = fminf(X1min, 0.f);
        }

        float y0 = s0 * ((s0 >= 0.f) ? X0max : X0min) + t0;
        float y1 = s1 * ((s1 >= 0.f) ? X1max : X1min) + t1;

        float2 r;
        r.x = fmaxf(y0, 0.f);
        r.y = fmaxf(y1, 0.f);
        ((float2*)out)[(size_t)n * (C_OUT_N / 2) + lane] = r;
    }
}

// ---------------- launch ----------------
extern "C" void kernel_launch(void* const* d_in, const int* in_sizes, int n_in,
                              void* d_out, int out_size)
{
    const float* voxels  = (const float*)d_in[0];
    const int*   npp     = (const int*)d_in[1];
    const float* centers = (const float*)d_in[2];
    const float* W       = (const float*)d_in[3];
    const float* gamma   = (const float*)d_in[4];
    const float* beta    = (const float*)d_in[5];
    float* out = (float*)d_out;

    int N = in_sizes[1];   // num_points_per_voxel has one entry per pillar

    k_zero<<<1, 64>>>();
    k_stats<<<(N + 255) / 256, 256>>>((const float4*)voxels, npp,
                                      (const float2*)centers, N);
    k_bn<<<1, 64>>>(W, gamma, beta, N);
    k_main<<<1184, 256>>>((const float4*)voxels, npp, (const float2*)centers,
                          W, out, N);
}

// round 3
// speedup vs baseline: 2.5170x; 2.5170x over previous
#include <cuda_runtime.h>
#include <cfloat>

#define P_PTS    32
#define C_OUT_N  64
#define NACC     54
#define BN_EPS   1e-3
#define NMAX     262144

typedef unsigned long long ull;

__device__ float  g_acc[NACC];
__device__ float  g_st[2 * C_OUT_N];   // s[64], t[64]
__device__ float4 g_mean[NMAX];        // per-pillar all-slot xyz sum / npts

// ---------------- f32x2 helpers (sm_100+) ----------------
__device__ __forceinline__ ull pack2(float lo, float hi) {
    ull r;
    asm("mov.b64 %0, {%1, %2};" : "=l"(r) : "f"(lo), "f"(hi));
    return r;
}
__device__ __forceinline__ void unpack2(ull v, float& lo, float& hi) {
    asm("mov.b64 {%0, %1}, %2;" : "=f"(lo), "=f"(hi) : "l"(v));
}
__device__ __forceinline__ ull ffma2(ull a, ull b, ull c) {
    ull d;
    asm("fma.rn.f32x2 %0, %1, %2, %3;" : "=l"(d) : "l"(a), "l"(b), "l"(c));
    return d;
}
__device__ __forceinline__ ull fmul2(ull a, ull b) {
    ull d;
    asm("mul.rn.f32x2 %0, %1, %2;" : "=l"(d) : "l"(a), "l"(b));
    return d;
}

// ---------------- kernel 0: zero the accumulators ----------------
__global__ void k_zero() {
    if (threadIdx.x < NACC) g_acc[threadIdx.x] = 0.0f;
}

// ---------------- kernel 1: global moment sums + per-pillar mean ----------------
// One thread per pillar. Reference quirk: points_mean sums ALL P slots (incl.
// garbage padding) then divides by npts -> u_xyz = sa_xyz/npts. Feature-side
// sums (sv, G1) are over VALID points only.
// Accumulators:
//   [0..3]   Sv (valid-point sums, 4 comps)
//   [4..5]   sum npts*cx, sum npts*cy
//   [6..15]  G1 sym 4x4 over valid pts
//   [16..35] G2[a][k] = sum_n sv_a * u_k  (u = mx,my,mz,cx,cy)
//   [36..50] G3 sym 5x5: sum_n npts * u_j * u_k (j<=k)
//   [51..53] Sa_xyz (all-slot xyz sums) = sum_n npts*u_xyz
__global__ void __launch_bounds__(256) k_stats(const float4* __restrict__ vox,
                                               const int* __restrict__ npp,
                                               const float2* __restrict__ cen,
                                               int N)
{
    __shared__ float sred[8][NACC];

    int n = blockIdx.x * blockDim.x + threadIdx.x;
    bool active = (n < N);
    int npts = 0;
    float cx = 0.f, cy = 0.f;
    if (active) {
        npts = npp[n];
        float2 c = cen[n];
        cx = c.x; cy = c.y;
    }

    float sv[4] = {0.f, 0.f, 0.f, 0.f};
    float sa[3] = {0.f, 0.f, 0.f};
    float g1[10];
#pragma unroll
    for (int i = 0; i < 10; i++) g1[i] = 0.f;

    const float4* base = vox + (size_t)n * P_PTS;
    int pmax = active ? P_PTS : 0;
    for (int p = 0; p < pmax; p++) {
        float4 v = base[p];
        sa[0] += v.x; sa[1] += v.y; sa[2] += v.z;
        if (p < npts) {
            sv[0] += v.x; sv[1] += v.y; sv[2] += v.z; sv[3] += v.w;
            g1[0] += v.x * v.x; g1[1] += v.x * v.y; g1[2] += v.x * v.z; g1[3] += v.x * v.w;
            g1[4] += v.y * v.y; g1[5] += v.y * v.z; g1[6] += v.y * v.w;
            g1[7] += v.z * v.z; g1[8] += v.z * v.w;
            g1[9] += v.w * v.w;
        }
    }

    float fn  = (float)npts;
    float inv = (npts > 0) ? (1.0f / fn) : 0.0f;
    float u[5] = {sa[0] * inv, sa[1] * inv, sa[2] * inv, cx, cy};

    if (active) g_mean[n] = make_float4(u[0], u[1], u[2], 0.f);

    float acc[NACC];
    acc[0] = sv[0]; acc[1] = sv[1]; acc[2] = sv[2]; acc[3] = sv[3];
    acc[4] = fn * cx; acc[5] = fn * cy;
#pragma unroll
    for (int i = 0; i < 10; i++) acc[6 + i] = g1[i];
    {
        int idx = 16;
#pragma unroll
        for (int a = 0; a < 4; a++)
#pragma unroll
            for (int k = 0; k < 5; k++) acc[idx++] = sv[a] * u[k];
#pragma unroll
        for (int j = 0; j < 5; j++)
#pragma unroll
            for (int k = j; k < 5; k++) acc[idx++] = fn * u[j] * u[k];
    }
    acc[51] = sa[0]; acc[52] = sa[1]; acc[53] = sa[2];

    // warp butterfly reduce
#pragma unroll
    for (int i = 0; i < NACC; i++) {
#pragma unroll
        for (int off = 16; off; off >>= 1)
            acc[i] += __shfl_xor_sync(0xffffffffu, acc[i], off);
    }
    int wid  = threadIdx.x >> 5;
    int lane = threadIdx.x & 31;
    if (lane == 0) {
#pragma unroll
        for (int i = 0; i < NACC; i++) sred[wid][i] = acc[i];
    }
    __syncthreads();
    // block reduce: one atomic per accumulator per block
    if (threadIdx.x < NACC) {
        float s = 0.f;
#pragma unroll
        for (int w = 0; w < 8; w++) s += sred[w][threadIdx.x];
        atomicAdd(&g_acc[threadIdx.x], s);
    }
}

// ---------------- kernel 2: solve BN affine per channel ----------------
__global__ void k_bn(const float* __restrict__ W,
                     const float* __restrict__ gamma,
                     const float* __restrict__ beta,
                     int N)
{
    int o = threadIdx.x;
    if (o >= C_OUT_N) return;

    double A[NACC];
    for (int i = 0; i < NACC; i++) A[i] = (double)g_acc[i];

    const float* w = W + o * 9;
    double w0 = w[0], w1 = w[1], w2 = w[2], w3 = w[3], w4 = w[4];
    double w5 = w[5], w6 = w[6], w7 = w[7], w8 = w[8];

    double Wp[4] = {w0 + w4 + w7, w1 + w5 + w8, w2 + w6, w3};
    double Wt[5] = {w4, w5, w6, w7, w8};

    double NP = (double)N * (double)P_PTS;

    double sumx = Wp[0] * A[0] + Wp[1] * A[1] + Wp[2] * A[2] + Wp[3] * A[3]
                - (Wt[0] * A[51] + Wt[1] * A[52] + Wt[2] * A[53]
                   + Wt[3] * A[4] + Wt[4] * A[5]);
    double mean = sumx / NP;

    const double* G1 = &A[6];
    double q1 = Wp[0] * Wp[0] * G1[0] + 2.0 * Wp[0] * Wp[1] * G1[1]
              + 2.0 * Wp[0] * Wp[2] * G1[2] + 2.0 * Wp[0] * Wp[3] * G1[3]
              + Wp[1] * Wp[1] * G1[4] + 2.0 * Wp[1] * Wp[2] * G1[5]
              + 2.0 * Wp[1] * Wp[3] * G1[6]
              + Wp[2] * Wp[2] * G1[7] + 2.0 * Wp[2] * Wp[3] * G1[8]
              + Wp[3] * Wp[3] * G1[9];

    double q2 = 0.0;
    for (int a = 0; a < 4; a++)
        for (int k = 0; k < 5; k++)
            q2 += Wp[a] * A[16 + a * 5 + k] * Wt[k];
    q2 *= -2.0;

    double q3 = 0.0;
    {
        int idx = 36;
        for (int j = 0; j < 5; j++)
            for (int k = j; k < 5; k++) {
                double f = (j == k) ? 1.0 : 2.0;
                q3 += f * Wt[j] * Wt[k] * A[idx++];
            }
    }

    double E2  = (q1 + q2 + q3) / NP;
    double var = E2 - mean * mean;
    double s   = (double)gamma[o] * rsqrt(var + BN_EPS);
    double t   = (double)beta[o] - mean * s;

    g_st[o]           = (float)s;
    g_st[C_OUT_N + o] = (float)t;
}

// ---------------- kernel 3: folded GEMM + max + BN + relu ----------------
// One warp per pillar (grid-stride). Lane l owns channels {2l, 2l+1} (f32x2).
// BN sign folded into the weights: track max of sign(s)*x only.
__global__ void __launch_bounds__(256) k_main(const float4* __restrict__ vox,
                                              const int* __restrict__ npp,
                                              const float* __restrict__ W,
                                              float* __restrict__ out,
                                              int N)
{
    __shared__ ull sdup[8][P_PTS * 4];

    int w    = threadIdx.x >> 5;
    int lane = threadIdx.x & 31;
    int warpsTotal = gridDim.x * 8;

    int o0 = lane * 2;
    const float* wr0 = W + o0 * 9;
    const float* wr1 = W + o0 * 9 + 9;

    float s0 = g_st[o0],           s1 = g_st[o0 + 1];
    float t0 = g_st[C_OUT_N + o0], t1 = g_st[C_OUT_N + o0 + 1];
    float sg0 = (s0 >= 0.f) ? 1.f : -1.f;
    float sg1 = (s1 >= 0.f) ? 1.f : -1.f;
    float as0 = fabsf(s0), as1 = fabsf(s1);

    // sign-folded GEMM weights (K=4 folded from K=9)
    ull wp0 = pack2(sg0 * (wr0[0] + wr0[4] + wr0[7]), sg1 * (wr1[0] + wr1[4] + wr1[7]));
    ull wp1 = pack2(sg0 * (wr0[1] + wr0[5] + wr0[8]), sg1 * (wr1[1] + wr1[5] + wr1[8]));
    ull wp2 = pack2(sg0 * (wr0[2] + wr0[6]),          sg1 * (wr1[2] + wr1[6]));
    ull wp3 = pack2(sg0 * wr0[3],                     sg1 * wr1[3]);

    // sign-folded, negated bias weights: b' = sum_k an_k * u_k = sg * (-a.u)
    ull an4 = pack2(-sg0 * wr0[4], -sg1 * wr1[4]);
    ull an5 = pack2(-sg0 * wr0[5], -sg1 * wr1[5]);
    ull an6 = pack2(-sg0 * wr0[6], -sg1 * wr1[6]);
    ull an7 = pack2(-sg0 * wr0[7], -sg1 * wr1[7]);
    ull an8 = pack2(-sg0 * wr0[8], -sg1 * wr1[8]);

    for (int n = blockIdx.x * 8 + w; n < N; n += warpsTotal) {
        int    npts = npp[n];
        float4 m    = g_mean[n];          // precomputed all-slot mean / npts
        float4 v    = vox[(size_t)n * P_PTS + lane];

        ull* sp = &sdup[w][lane * 4];
        sp[0] = pack2(v.x, v.x);
        sp[1] = pack2(v.y, v.y);
        sp[2] = pack2(v.z, v.z);
        sp[3] = pack2(v.w, v.w);
        __syncwarp();

        // packed bias (u = mx,my,mz,cx,cy); cx,cy stashed via centers? folded below
        ull b = ffma2(an4, pack2(m.x, m.x),
                ffma2(an5, pack2(m.y, m.y),
                ffma2(an6, pack2(m.z, m.z), 0ull)));

        float maxx0 = -FLT_MAX, maxx1 = -FLT_MAX;
        const ulonglong2* sq = (const ulonglong2*)&sdup[w][0];
#pragma unroll 4
        for (int p = 0; p < npts; p++) {
            ulonglong2 q01 = sq[p * 2];
            ulonglong2 q23 = sq[p * 2 + 1];
            ull x = ffma2(q01.x, wp0,
                    ffma2(q01.y, wp1,
                    ffma2(q23.x, wp2,
                    fmul2(q23.y, wp3))));
            float x0, x1;
            unpack2(x, x0, x1);
            maxx0 = fmaxf(maxx0, x0);
            maxx1 = fmaxf(maxx1, x1);
        }
        __syncwarp();

        float b0, b1;
        unpack2(b, b0, b1);
        // center part of bias (cx,cy) — add scalar (saves smem traffic)
        // NOTE: centers folded here via an7/an8 loads below
        float X0 = maxx0 + b0;
        float X1 = maxx1 + b1;
        if (npts < P_PTS) { X0 = fmaxf(X0, 0.f); X1 = fmaxf(X1, 0.f); }

        float y0 = fmaxf(as0 * X0 + t0, 0.f);
        float y1 = fmaxf(as1 * X1 + t1, 0.f);
        ((float2*)out)[(size_t)n * (C_OUT_N / 2) + lane] = make_float2(y0, y1);
    }
    (void)an7; (void)an8;
}

// k_main above needs centers in the bias; pass them via a variant that keeps
// the center terms. To avoid a missed term we use this corrected kernel:
__global__ void __launch_bounds__(256) k_main2(const float4* __restrict__ vox,
                                               const int* __restrict__ npp,
                                               const float2* __restrict__ cen,
                                               const float* __restrict__ W,
                                               float* __restrict__ out,
                                               int N)
{
    __shared__ ull sdup[8][P_PTS * 4];

    int w    = threadIdx.x >> 5;
    int lane = threadIdx.x & 31;
    int warpsTotal = gridDim.x * 8;

    int o0 = lane * 2;
    const float* wr0 = W + o0 * 9;
    const float* wr1 = W + o0 * 9 + 9;

    float s0 = g_st[o0],           s1 = g_st[o0 + 1];
    float t0 = g_st[C_OUT_N + o0], t1 = g_st[C_OUT_N + o0 + 1];
    float sg0 = (s0 >= 0.f) ? 1.f : -1.f;
    float sg1 = (s1 >= 0.f) ? 1.f : -1.f;
    float as0 = fabsf(s0), as1 = fabsf(s1);

    ull wp0 = pack2(sg0 * (wr0[0] + wr0[4] + wr0[7]), sg1 * (wr1[0] + wr1[4] + wr1[7]));
    ull wp1 = pack2(sg0 * (wr0[1] + wr0[5] + wr0[8]), sg1 * (wr1[1] + wr1[5] + wr1[8]));
    ull wp2 = pack2(sg0 * (wr0[2] + wr0[6]),          sg1 * (wr1[2] + wr1[6]));
    ull wp3 = pack2(sg0 * wr0[3],                     sg1 * wr1[3]);

    ull an4 = pack2(-sg0 * wr0[4], -sg1 * wr1[4]);
    ull an5 = pack2(-sg0 * wr0[5], -sg1 * wr1[5]);
    ull an6 = pack2(-sg0 * wr0[6], -sg1 * wr1[6]);
    ull an7 = pack2(-sg0 * wr0[7], -sg1 * wr1[7]);
    ull an8 = pack2(-sg0 * wr0[8], -sg1 * wr1[8]);

    for (int n = blockIdx.x * 8 + w; n < N; n += warpsTotal) {
        int    npts = npp[n];
        float2 c    = cen[n];
        float4 m    = g_mean[n];
        float4 v    = vox[(size_t)n * P_PTS + lane];

        ull* sp = &sdup[w][lane * 4];
        sp[0] = pack2(v.x, v.x);
        sp[1] = pack2(v.y, v.y);
        sp[2] = pack2(v.z, v.z);
        sp[3] = pack2(v.w, v.w);
        __syncwarp();

        ull b = ffma2(an4, pack2(m.x, m.x),
                ffma2(an5, pack2(m.y, m.y),
                ffma2(an6, pack2(m.z, m.z),
                ffma2(an7, pack2(c.x, c.x),
                fmul2(an8, pack2(c.y, c.y))))));

        float maxx0 = -FLT_MAX, maxx1 = -FLT_MAX;
        const ulonglong2* sq = (const ulonglong2*)&sdup[w][0];
#pragma unroll 4
        for (int p = 0; p < npts; p++) {
            ulonglong2 q01 = sq[p * 2];
            ulonglong2 q23 = sq[p * 2 + 1];
            ull x = ffma2(q01.x, wp0,
                    ffma2(q01.y, wp1,
                    ffma2(q23.x, wp2,
                    fmul2(q23.y, wp3))));
            float x0, x1;
            unpack2(x, x0, x1);
            maxx0 = fmaxf(maxx0, x0);
            maxx1 = fmaxf(maxx1, x1);
        }
        __syncwarp();

        float b0, b1;
        unpack2(b, b0, b1);
        float X0 = maxx0 + b0;
        float X1 = maxx1 + b1;
        if (npts < P_PTS) { X0 = fmaxf(X0, 0.f); X1 = fmaxf(X1, 0.f); }

        float y0 = fmaxf(as0 * X0 + t0, 0.f);
        float y1 = fmaxf(as1 * X1 + t1, 0.f);
        ((float2*)out)[(size_t)n * (C_OUT_N / 2) + lane] = make_float2(y0, y1);
    }
}

// ---------------- launch ----------------
extern "C" void kernel_launch(void* const* d_in, const int* in_sizes, int n_in,
                              void* d_out, int out_size)
{
    const float* voxels  = (const float*)d_in[0];
    const int*   npp     = (const int*)d_in[1];
    const float* centers = (const float*)d_in[2];
    const float* W       = (const float*)d_in[3];
    const float* gamma   = (const float*)d_in[4];
    const float* beta    = (const float*)d_in[5];
    float* out = (float*)d_out;

    int N = in_sizes[1];

    k_zero<<<1, 64>>>();
    k_stats<<<(N + 255) / 256, 256>>>((const float4*)voxels, npp,
                                      (const float2*)centers, N);
    k_bn<<<1, 64>>>(W, gamma, beta, N);
    k_main2<<<1184, 256>>>((const float4*)voxels, npp, (const float2*)centers,
                           W, out, N);
}

// round 4
// speedup vs baseline: 2.6833x; 1.0661x over previous
#include <cuda_runtime.h>
#include <cfloat>

#define P_PTS    32
#define C_OUT_N  64
#define NACC     54
#define BN_EPS   1e-3
#define NMAX     262144
#define SW       33            // float4 stride per staged pillar (bank-conflict pad)

typedef unsigned long long ull;

__device__ float  g_acc[NACC];
__device__ float  g_st[2 * C_OUT_N];   // s[64], t[64]
__device__ float4 g_mean[NMAX];        // per-pillar all-slot xyz sum / npts

// ---------------- f32x2 helpers (sm_100+) ----------------
__device__ __forceinline__ ull pack2(float lo, float hi) {
    ull r;
    asm("mov.b64 %0, {%1, %2};" : "=l"(r) : "f"(lo), "f"(hi));
    return r;
}
__device__ __forceinline__ void unpack2(ull v, float& lo, float& hi) {
    asm("mov.b64 {%0, %1}, %2;" : "=f"(lo), "=f"(hi) : "l"(v));
}
__device__ __forceinline__ ull ffma2(ull a, ull b, ull c) {
    ull d;
    asm("fma.rn.f32x2 %0, %1, %2, %3;" : "=l"(d) : "l"(a), "l"(b), "l"(c));
    return d;
}
__device__ __forceinline__ ull fmul2(ull a, ull b) {
    ull d;
    asm("mul.rn.f32x2 %0, %1, %2;" : "=l"(d) : "l"(a), "l"(b));
    return d;
}

// ---------------- kernel 0: zero the accumulators ----------------
__global__ void k_zero() {
    if (threadIdx.x < NACC) g_acc[threadIdx.x] = 0.0f;
}

// ---------------- kernel 1: moment sums (coalesced, smem-staged) ----------------
// 64-thread blocks, 2 warps. Each warp stages 32 pillars into smem with
// coalesced LDG.128 (lane l = point l of pillar q), then lane l processes
// pillar (base+l) out of smem (SW=33 pad -> conflict-free per 8-lane phase).
// Reference quirk preserved: u_xyz = (sum over ALL 32 slots)/npts; feature-side
// sums over valid points only.
__global__ void __launch_bounds__(64) k_stats(const float4* __restrict__ vox,
                                              const int* __restrict__ npp,
                                              const float2* __restrict__ cen,
                                              int N)
{
    __shared__ float4 stg[2][32 * SW];
    __shared__ float  sred[2][NACC];

    int w    = threadIdx.x >> 5;
    int lane = threadIdx.x & 31;
    int pillarBase = blockIdx.x * 64 + w * 32;

    // stage 32 pillars, coalesced
    float4* buf = stg[w];
#pragma unroll 8
    for (int q = 0; q < 32; q++) {
        int pn = pillarBase + q;
        if (pn < N) buf[q * SW + lane] = vox[(size_t)pn * P_PTS + lane];
    }
    __syncwarp();

    int n = pillarBase + lane;
    bool active = (n < N);
    int npts = 0;
    float cx = 0.f, cy = 0.f;
    if (active) {
        npts = npp[n];
        float2 c = cen[n];
        cx = c.x; cy = c.y;
    }

    float sv[4] = {0.f, 0.f, 0.f, 0.f};
    float sa[3] = {0.f, 0.f, 0.f};
    float g1[10];
#pragma unroll
    for (int i = 0; i < 10; i++) g1[i] = 0.f;

    const float4* my = &buf[lane * SW];
#pragma unroll 8
    for (int p = 0; p < P_PTS; p++) {
        float4 v = my[p];
        if (active) {
            sa[0] += v.x; sa[1] += v.y; sa[2] += v.z;
            if (p < npts) {
                sv[0] += v.x; sv[1] += v.y; sv[2] += v.z; sv[3] += v.w;
                g1[0] += v.x * v.x; g1[1] += v.x * v.y; g1[2] += v.x * v.z; g1[3] += v.x * v.w;
                g1[4] += v.y * v.y; g1[5] += v.y * v.z; g1[6] += v.y * v.w;
                g1[7] += v.z * v.z; g1[8] += v.z * v.w;
                g1[9] += v.w * v.w;
            }
        }
    }

    float fn  = (float)npts;
    float inv = (npts > 0) ? (1.0f / fn) : 0.0f;
    float u[5] = {sa[0] * inv, sa[1] * inv, sa[2] * inv, cx, cy};

    if (active) g_mean[n] = make_float4(u[0], u[1], u[2], 0.f);

    float acc[NACC];
    acc[0] = sv[0]; acc[1] = sv[1]; acc[2] = sv[2]; acc[3] = sv[3];
    acc[4] = fn * cx; acc[5] = fn * cy;
#pragma unroll
    for (int i = 0; i < 10; i++) acc[6 + i] = g1[i];
    {
        int idx = 16;
#pragma unroll
        for (int a = 0; a < 4; a++)
#pragma unroll
            for (int k = 0; k < 5; k++) acc[idx++] = sv[a] * u[k];
#pragma unroll
        for (int j = 0; j < 5; j++)
#pragma unroll
            for (int k = j; k < 5; k++) acc[idx++] = fn * u[j] * u[k];
    }
    acc[51] = sa[0]; acc[52] = sa[1]; acc[53] = sa[2];

#pragma unroll
    for (int i = 0; i < NACC; i++) {
#pragma unroll
        for (int off = 16; off; off >>= 1)
            acc[i] += __shfl_xor_sync(0xffffffffu, acc[i], off);
    }
    if (lane == 0) {
#pragma unroll
        for (int i = 0; i < NACC; i++) sred[w][i] = acc[i];
    }
    __syncthreads();
    if (threadIdx.x < NACC)
        atomicAdd(&g_acc[threadIdx.x], sred[0][threadIdx.x] + sred[1][threadIdx.x]);
}

// ---------------- kernel 2: solve BN affine per channel ----------------
__global__ void k_bn(const float* __restrict__ W,
                     const float* __restrict__ gamma,
                     const float* __restrict__ beta,
                     int N)
{
    int o = threadIdx.x;
    if (o >= C_OUT_N) return;

    double A[NACC];
    for (int i = 0; i < NACC; i++) A[i] = (double)g_acc[i];

    const float* w = W + o * 9;
    double w0 = w[0], w1 = w[1], w2 = w[2], w3 = w[3], w4 = w[4];
    double w5 = w[5], w6 = w[6], w7 = w[7], w8 = w[8];

    double Wp[4] = {w0 + w4 + w7, w1 + w5 + w8, w2 + w6, w3};
    double Wt[5] = {w4, w5, w6, w7, w8};

    double NP = (double)N * (double)P_PTS;

    double sumx = Wp[0] * A[0] + Wp[1] * A[1] + Wp[2] * A[2] + Wp[3] * A[3]
                - (Wt[0] * A[51] + Wt[1] * A[52] + Wt[2] * A[53]
                   + Wt[3] * A[4] + Wt[4] * A[5]);
    double mean = sumx / NP;

    const double* G1 = &A[6];
    double q1 = Wp[0] * Wp[0] * G1[0] + 2.0 * Wp[0] * Wp[1] * G1[1]
              + 2.0 * Wp[0] * Wp[2] * G1[2] + 2.0 * Wp[0] * Wp[3] * G1[3]
              + Wp[1] * Wp[1] * G1[4] + 2.0 * Wp[1] * Wp[2] * G1[5]
              + 2.0 * Wp[1] * Wp[3] * G1[6]
              + Wp[2] * Wp[2] * G1[7] + 2.0 * Wp[2] * Wp[3] * G1[8]
              + Wp[3] * Wp[3] * G1[9];

    double q2 = 0.0;
    for (int a = 0; a < 4; a++)
        for (int k = 0; k < 5; k++)
            q2 += Wp[a] * A[16 + a * 5 + k] * Wt[k];
    q2 *= -2.0;

    double q3 = 0.0;
    {
        int idx = 36;
        for (int j = 0; j < 5; j++)
            for (int k = j; k < 5; k++) {
                double f = (j == k) ? 1.0 : 2.0;
                q3 += f * Wt[j] * Wt[k] * A[idx++];
            }
    }

    double E2  = (q1 + q2 + q3) / NP;
    double var = E2 - mean * mean;
    double s   = (double)gamma[o] * rsqrt(var + BN_EPS);
    double t   = (double)beta[o] - mean * s;

    g_st[o]           = (float)s;
    g_st[C_OUT_N + o] = (float)t;
}

// ---------------- kernel 3: folded GEMM + max + BN + relu ----------------
// One warp per pillar (grid-stride), 1-deep prefetch of the next pillar's
// loads. Lane l owns channels {2l,2l+1} via f32x2; BN sign folded into weights.
__global__ void __launch_bounds__(256) k_main(const float4* __restrict__ vox,
                                              const int* __restrict__ npp,
                                              const float2* __restrict__ cen,
                                              const float* __restrict__ W,
                                              float* __restrict__ out,
                                              int N)
{
    __shared__ ull sdup[8][P_PTS * 4];

    int w    = threadIdx.x >> 5;
    int lane = threadIdx.x & 31;
    int stride = gridDim.x * 8;

    int o0 = lane * 2;
    const float* wr0 = W + o0 * 9;
    const float* wr1 = W + o0 * 9 + 9;

    float s0 = g_st[o0],           s1 = g_st[o0 + 1];
    float t0 = g_st[C_OUT_N + o0], t1 = g_st[C_OUT_N + o0 + 1];
    float sg0 = (s0 >= 0.f) ? 1.f : -1.f;
    float sg1 = (s1 >= 0.f) ? 1.f : -1.f;
    float as0 = fabsf(s0), as1 = fabsf(s1);

    ull wp0 = pack2(sg0 * (wr0[0] + wr0[4] + wr0[7]), sg1 * (wr1[0] + wr1[4] + wr1[7]));
    ull wp1 = pack2(sg0 * (wr0[1] + wr0[5] + wr0[8]), sg1 * (wr1[1] + wr1[5] + wr1[8]));
    ull wp2 = pack2(sg0 * (wr0[2] + wr0[6]),          sg1 * (wr1[2] + wr1[6]));
    ull wp3 = pack2(sg0 * wr0[3],                     sg1 * wr1[3]);

    ull an4 = pack2(-sg0 * wr0[4], -sg1 * wr1[4]);
    ull an5 = pack2(-sg0 * wr0[5], -sg1 * wr1[5]);
    ull an6 = pack2(-sg0 * wr0[6], -sg1 * wr1[6]);
    ull an7 = pack2(-sg0 * wr0[7], -sg1 * wr1[7]);
    ull an8 = pack2(-sg0 * wr0[8], -sg1 * wr1[8]);

    int n = blockIdx.x * 8 + w;
    if (n >= N) return;

    // prologue loads
    int    npts = npp[n];
    float2 c    = cen[n];
    float4 m    = g_mean[n];
    float4 v    = vox[(size_t)n * P_PTS + lane];

    while (true) {
        // prefetch next pillar
        int n2 = n + stride;
        bool more = (n2 < N);
        int npts2 = 0; float2 c2 = make_float2(0.f, 0.f);
        float4 m2 = make_float4(0.f, 0.f, 0.f, 0.f);
        float4 v2 = m2;
        if (more) {
            npts2 = npp[n2];
            c2 = cen[n2];
            m2 = g_mean[n2];
            v2 = vox[(size_t)n2 * P_PTS + lane];
        }

        // stage current pillar (duplicated for f32x2 broadcast), 2x STS.128
        ulonglong2* sp = (ulonglong2*)&sdup[w][lane * 4];
        sp[0] = make_ulonglong2(pack2(v.x, v.x), pack2(v.y, v.y));
        sp[1] = make_ulonglong2(pack2(v.z, v.z), pack2(v.w, v.w));
        __syncwarp();

        ull b = ffma2(an4, pack2(m.x, m.x),
                ffma2(an5, pack2(m.y, m.y),
                ffma2(an6, pack2(m.z, m.z),
                ffma2(an7, pack2(c.x, c.x),
                fmul2(an8, pack2(c.y, c.y))))));

        float maxx0 = -FLT_MAX, maxx1 = -FLT_MAX;
        const ulonglong2* sq = (const ulonglong2*)&sdup[w][0];
#pragma unroll 4
        for (int p = 0; p < npts; p++) {
            ulonglong2 q01 = sq[p * 2];
            ulonglong2 q23 = sq[p * 2 + 1];
            ull x = ffma2(q01.x, wp0,
                    ffma2(q01.y, wp1,
                    ffma2(q23.x, wp2,
                    fmul2(q23.y, wp3))));
            float x0, x1;
            unpack2(x, x0, x1);
            maxx0 = fmaxf(maxx0, x0);
            maxx1 = fmaxf(maxx1, x1);
        }

        float b0, b1;
        unpack2(b, b0, b1);
        float X0 = maxx0 + b0;
        float X1 = maxx1 + b1;
        if (npts < P_PTS) { X0 = fmaxf(X0, 0.f); X1 = fmaxf(X1, 0.f); }

        float y0 = fmaxf(as0 * X0 + t0, 0.f);
        float y1 = fmaxf(as1 * X1 + t1, 0.f);
        ((float2*)out)[(size_t)n * (C_OUT_N / 2) + lane] = make_float2(y0, y1);

        if (!more) break;
        __syncwarp();        // loop reads done before next staging overwrites
        n = n2; npts = npts2; c = c2; m = m2; v = v2;
    }
}

// ---------------- launch ----------------
extern "C" void kernel_launch(void* const* d_in, const int* in_sizes, int n_in,
                              void* d_out, int out_size)
{
    const float* voxels  = (const float*)d_in[0];
    const int*   npp     = (const int*)d_in[1];
    const float* centers = (const float*)d_in[2];
    const float* W       = (const float*)d_in[3];
    const float* gamma   = (const float*)d_in[4];
    const float* beta    = (const float*)d_in[5];
    float* out = (float*)d_out;

    int N = in_sizes[1];

    k_zero<<<1, 64>>>();
    k_stats<<<(N + 63) / 64, 64>>>((const float4*)voxels, npp,
                                   (const float2*)centers, N);
    k_bn<<<1, 64>>>(W, gamma, beta, N);
    k_main<<<1184, 256>>>((const float4*)voxels, npp, (const float2*)centers,
                          W, out, N);
}

// round 6
// speedup vs baseline: 2.9426x; 1.0966x over previous
#include <cuda_runtime.h>
#include <cfloat>

#define P_PTS    32
#define C_OUT_N  64
#define NACC     54
#define BN_EPS   1e-3
#define NMAX     262144
#define SW2      17            // float4 stride per staged pillar chunk (pad)

typedef unsigned long long ull;

__device__ float  g_acc[NACC];
__device__ float  g_st[2 * C_OUT_N];   // s[64], t[64]
__device__ float4 g_mean[NMAX];        // per-pillar all-slot xyz sum / npts

// ---------------- f32x2 helpers (sm_100+) ----------------
__device__ __forceinline__ ull pack2(float lo, float hi) {
    ull r;
    asm("mov.b64 %0, {%1, %2};" : "=l"(r) : "f"(lo), "f"(hi));
    return r;
}
__device__ __forceinline__ void unpack2(ull v, float& lo, float& hi) {
    asm("mov.b64 {%0, %1}, %2;" : "=f"(lo), "=f"(hi) : "l"(v));
}
__device__ __forceinline__ ull ffma2(ull a, ull b, ull c) {
    ull d;
    asm("fma.rn.f32x2 %0, %1, %2, %3;" : "=l"(d) : "l"(a), "l"(b), "l"(c));
    return d;
}
__device__ __forceinline__ ull fmul2(ull a, ull b) {
    ull d;
    asm("mul.rn.f32x2 %0, %1, %2;" : "=l"(d) : "l"(a), "l"(b));
    return d;
}

// ---------------- kernel 0: zero the accumulators ----------------
__global__ void k_zero() {
    if (threadIdx.x < NACC) g_acc[threadIdx.x] = 0.0f;
}

// ---------------- kernel 1: moment sums (coalesced, chunked smem staging) ----
// 64-thread blocks, 2 warps, each warp owns 32 pillars. Points staged in two
// 16-point chunks (halves smem -> more blocks/SM resident). Staging is
// coalesced (2 pillars x 16 points per LDG round); processing is
// thread-per-pillar out of smem (SW2=17 pad -> conflict-free per phase).
// Reference quirk preserved: u_xyz = (sum over ALL 32 slots)/npts;
// feature-side sums over valid points only.
__global__ void __launch_bounds__(64) k_stats(const float4* __restrict__ vox,
                                              const int* __restrict__ npp,
                                              const float2* __restrict__ cen,
                                              int N)
{
    __shared__ float4 stg[2][32 * SW2];
    __shared__ float  sred[2][NACC];

    int w    = threadIdx.x >> 5;
    int lane = threadIdx.x & 31;
    int pillarBase = blockIdx.x * 64 + w * 32;

    int n = pillarBase + lane;
    bool active = (n < N);
    int npts = 0;
    float cx = 0.f, cy = 0.f;
    if (active) {
        npts = npp[n];
        float2 c = cen[n];
        cx = c.x; cy = c.y;
    }

    float sv[4] = {0.f, 0.f, 0.f, 0.f};
    float sa[3] = {0.f, 0.f, 0.f};
    float g1[10];
#pragma unroll
    for (int i = 0; i < 10; i++) g1[i] = 0.f;

    float4* buf = stg[w];
    int half = lane >> 4;          // which pillar of the pair
    int pt   = lane & 15;          // which point within the chunk

    for (int ck = 0; ck < 2; ck++) {
        // stage: 16 rounds x (2 pillars x 16 points) coalesced
#pragma unroll 4
        for (int q = 0; q < 16; q++) {
            int pidx = pillarBase + 2 * q + half;
            if (pidx < N)
                buf[(2 * q + half) * SW2 + pt] =
                    vox[(size_t)pidx * P_PTS + ck * 16 + pt];
        }
        __syncwarp();

        const float4* my = &buf[lane * SW2];
#pragma unroll 8
        for (int p = 0; p < 16; p++) {
            float4 v = my[p];
            int gp = ck * 16 + p;
            if (active) {
                sa[0] += v.x; sa[1] += v.y; sa[2] += v.z;
                if (gp < npts) {
                    sv[0] += v.x; sv[1] += v.y; sv[2] += v.z; sv[3] += v.w;
                    g1[0] += v.x * v.x; g1[1] += v.x * v.y; g1[2] += v.x * v.z; g1[3] += v.x * v.w;
                    g1[4] += v.y * v.y; g1[5] += v.y * v.z; g1[6] += v.y * v.w;
                    g1[7] += v.z * v.z; g1[8] += v.z * v.w;
                    g1[9] += v.w * v.w;
                }
            }
        }
        __syncwarp();
    }

    float fn  = (float)npts;
    float inv = (npts > 0) ? (1.0f / fn) : 0.0f;
    float u[5] = {sa[0] * inv, sa[1] * inv, sa[2] * inv, cx, cy};

    if (active) g_mean[n] = make_float4(u[0], u[1], u[2], 0.f);

    float acc[NACC];
    acc[0] = sv[0]; acc[1] = sv[1]; acc[2] = sv[2]; acc[3] = sv[3];
    acc[4] = fn * cx; acc[5] = fn * cy;
#pragma unroll
    for (int i = 0; i < 10; i++) acc[6 + i] = g1[i];
    {
        int idx = 16;
#pragma unroll
        for (int a = 0; a < 4; a++)
#pragma unroll
            for (int k = 0; k < 5; k++) acc[idx++] = sv[a] * u[k];
#pragma unroll
        for (int j = 0; j < 5; j++)
#pragma unroll
            for (int k = j; k < 5; k++) acc[idx++] = fn * u[j] * u[k];
    }
    acc[51] = sa[0]; acc[52] = sa[1]; acc[53] = sa[2];

#pragma unroll
    for (int i = 0; i < NACC; i++) {
#pragma unroll
        for (int off = 16; off; off >>= 1)
            acc[i] += __shfl_xor_sync(0xffffffffu, acc[i], off);
    }
    if (lane == 0) {
#pragma unroll
        for (int i = 0; i < NACC; i++) sred[w][i] = acc[i];
    }
    __syncthreads();
    if (threadIdx.x < NACC)
        atomicAdd(&g_acc[threadIdx.x], sred[0][threadIdx.x] + sred[1][threadIdx.x]);
}

// ---------------- kernel 2: solve BN affine per channel ----------------
__global__ void k_bn(const float* __restrict__ W,
                     const float* __restrict__ gamma,
                     const float* __restrict__ beta,
                     int N)
{
    int o = threadIdx.x;
    if (o >= C_OUT_N) return;

    double A[NACC];
    for (int i = 0; i < NACC; i++) A[i] = (double)g_acc[i];

    const float* w = W + o * 9;
    double w0 = w[0], w1 = w[1], w2 = w[2], w3 = w[3], w4 = w[4];
    double w5 = w[5], w6 = w[6], w7 = w[7], w8 = w[8];

    double Wp[4] = {w0 + w4 + w7, w1 + w5 + w8, w2 + w6, w3};
    double Wt[5] = {w4, w5, w6, w7, w8};

    double NP = (double)N * (double)P_PTS;

    double sumx = Wp[0] * A[0] + Wp[1] * A[1] + Wp[2] * A[2] + Wp[3] * A[3]
                - (Wt[0] * A[51] + Wt[1] * A[52] + Wt[2] * A[53]
                   + Wt[3] * A[4] + Wt[4] * A[5]);
    double mean = sumx / NP;

    const double* G1 = &A[6];
    double q1 = Wp[0] * Wp[0] * G1[0] + 2.0 * Wp[0] * Wp[1] * G1[1]
              + 2.0 * Wp[0] * Wp[2] * G1[2] + 2.0 * Wp[0] * Wp[3] * G1[3]
              + Wp[1] * Wp[1] * G1[4] + 2.0 * Wp[1] * Wp[2] * G1[5]
              + 2.0 * Wp[1] * Wp[3] * G1[6]
              + Wp[2] * Wp[2] * G1[7] + 2.0 * Wp[2] * Wp[3] * G1[8]
              + Wp[3] * Wp[3] * G1[9];

    double q2 = 0.0;
    for (int a = 0; a < 4; a++)
        for (int k = 0; k < 5; k++)
            q2 += Wp[a] * A[16 + a * 5 + k] * Wt[k];
    q2 *= -2.0;

    double q3 = 0.0;
    {
        int idx = 36;
        for (int j = 0; j < 5; j++)
            for (int k = j; k < 5; k++) {
                double f = (j == k) ? 1.0 : 2.0;
                q3 += f * Wt[j] * Wt[k] * A[idx++];
            }
    }

    double E2  = (q1 + q2 + q3) / NP;
    double var = E2 - mean * mean;
    double s   = (double)gamma[o] * rsqrt(var + BN_EPS);
    double t   = (double)beta[o] - mean * s;

    g_st[o]           = (float)s;
    g_st[C_OUT_N + o] = (float)t;
}

// ---------------- kernel 3: folded GEMM + max + BN + relu ----------------
// One warp per pillar (grid-stride), SoA point-packed f32x2:
//   lane l owns channels {l, l+32}; points packed in pairs as f32x2.
//   Tile staged as 4 SoA float arrays; PADDED SLOTS STAGED AS NaN so the
//   remainder-rounded loop's extra slots are ignored by fmaxf (returns the
//   non-NaN operand). Padded feature rows (x=0 in the reference) are handled
//   by the post-bias fmax(X, 0) epilogue.
__global__ void __launch_bounds__(256) k_main(const float4* __restrict__ vox,
                                              const int* __restrict__ npp,
                                              const float2* __restrict__ cen,
                                              const float* __restrict__ W,
                                              float* __restrict__ out,
                                              int N)
{
    __shared__ float stile[8][4][P_PTS];   // [warp][comp][point]

    int w    = threadIdx.x >> 5;
    int lane = threadIdx.x & 31;
    int stride = gridDim.x * 8;

    int c0 = lane, c1 = lane + 32;
    const float* wr0 = W + c0 * 9;
    const float* wr1 = W + c1 * 9;

    float s0 = g_st[c0],           s1 = g_st[c1];
    float t0 = g_st[C_OUT_N + c0], t1 = g_st[C_OUT_N + c1];
    float sg0 = (s0 >= 0.f) ? 1.f : -1.f;
    float sg1 = (s1 >= 0.f) ? 1.f : -1.f;
    float as0 = fabsf(s0), as1 = fabsf(s1);

    // bias weights (scalar; bias computed per pillar outside the loop)
    float a04 = wr0[4], a05 = wr0[5], a06 = wr0[6], a07 = wr0[7], a08 = wr0[8];
    float a14 = wr1[4], a15 = wr1[5], a16 = wr1[6], a17 = wr1[7], a18 = wr1[8];

    // sign-folded, duplicated GEMM weights (same value in both f32x2 halves)
    float f00 = sg0 * (wr0[0] + a04 + a07);
    float f01 = sg0 * (wr0[1] + a05 + a08);
    float f02 = sg0 * (wr0[2] + a06);
    float f03 = sg0 * wr0[3];
    float f10 = sg1 * (wr1[0] + a14 + a17);
    float f11 = sg1 * (wr1[1] + a15 + a18);
    float f12 = sg1 * (wr1[2] + a16);
    float f13 = sg1 * wr1[3];
    ull w00 = pack2(f00, f00), w10 = pack2(f01, f01);
    ull w20 = pack2(f02, f02), w30 = pack2(f03, f03);
    ull w01 = pack2(f10, f10), w11 = pack2(f11, f11);
    ull w21 = pack2(f12, f12), w31 = pack2(f13, f13);

    float* sx  = stile[w][0];
    float* sy  = stile[w][1];
    float* sz  = stile[w][2];
    float* swv = stile[w][3];

    const float nanv = __int_as_float(0x7fffffff);

    int n = blockIdx.x * 8 + w;
    if (n >= N) return;

    // prologue loads
    int    npts = npp[n];
    float2 c    = cen[n];
    float4 m    = g_mean[n];
    float4 v    = vox[(size_t)n * P_PTS + lane];

    while (true) {
        // prefetch next pillar
        int n2 = n + stride;
        bool more = (n2 < N);
        int npts2 = 0; float2 c2 = make_float2(0.f, 0.f);
        float4 m2 = make_float4(0.f, 0.f, 0.f, 0.f);
        float4 v2 = m2;
        if (more) {
            npts2 = npp[n2];
            c2 = cen[n2];
            m2 = g_mean[n2];
            v2 = vox[(size_t)n2 * P_PTS + lane];
        }

        // stage SoA; padded slots become NaN (ignored by fmaxf in the loop)
        bool valid = (lane < npts);
        sx[lane]  = valid ? v.x : nanv;
        sy[lane]  = valid ? v.y : nanv;
        sz[lane]  = valid ? v.z : nanv;
        swv[lane] = valid ? v.w : nanv;
        __syncwarp();

        // per-pillar bias for this lane's two channels (sign-folded)
        float b0 = -sg0 * (a04 * m.x + a05 * m.y + a06 * m.z + a07 * c.x + a08 * c.y);
        float b1 = -sg1 * (a14 * m.x + a15 * m.y + a16 * m.z + a17 * c.x + a18 * c.y);

        int nloop = (npts + 3) & ~3;      // NaN slots beyond npts are ignored

        float m0a = -FLT_MAX, m0b = -FLT_MAX;
        float m1a = -FLT_MAX, m1b = -FLT_MAX;

        for (int p = 0; p < nloop; p += 4) {
            ulonglong2 qx = *(const ulonglong2*)(sx + p);
            ulonglong2 qy = *(const ulonglong2*)(sy + p);
            ulonglong2 qz = *(const ulonglong2*)(sz + p);
            ulonglong2 qw = *(const ulonglong2*)(swv + p);

            ull rA0 = ffma2(qx.x, w00, ffma2(qy.x, w10, ffma2(qz.x, w20, fmul2(qw.x, w30))));
            ull rB0 = ffma2(qx.y, w00, ffma2(qy.y, w10, ffma2(qz.y, w20, fmul2(qw.y, w30))));
            ull rA1 = ffma2(qx.x, w01, ffma2(qy.x, w11, ffma2(qz.x, w21, fmul2(qw.x, w31))));
            ull rB1 = ffma2(qx.y, w01, ffma2(qy.y, w11, ffma2(qz.y, w21, fmul2(qw.y, w31))));

            float lo, hi;
            unpack2(rA0, lo, hi); m0a = fmaxf(m0a, fmaxf(lo, hi));
            unpack2(rB0, lo, hi); m0b = fmaxf(m0b, fmaxf(lo, hi));
            unpack2(rA1, lo, hi); m1a = fmaxf(m1a, fmaxf(lo, hi));
            unpack2(rB1, lo, hi); m1b = fmaxf(m1b, fmaxf(lo, hi));
        }
        __syncwarp();   // tile reads done before next iteration restages

        float X0 = fmaxf(m0a, m0b) + b0;
        float X1 = fmaxf(m1a, m1b) + b1;
        if (npts < P_PTS) {   // reference's padded rows contribute x = 0
            X0 = fmaxf(X0, 0.f);
            X1 = fmaxf(X1, 0.f);
        }

        float y0 = fmaxf(as0 * X0 + t0, 0.f);
        float y1 = fmaxf(as1 * X1 + t1, 0.f);
        out[(size_t)n * C_OUT_N + c0] = y0;
        out[(size_t)n * C_OUT_N + c1] = y1;

        if (!more) break;
        n = n2; npts = npts2; c = c2; m = m2; v = v2;
    }
}

// ---------------- launch ----------------
extern "C" void kernel_launch(void* const* d_in, const int* in_sizes, int n_in,
                              void* d_out, int out_size)
{
    const float* voxels  = (const float*)d_in[0];
    const int*   npp     = (const int*)d_in[1];
    const float* centers = (const float*)d_in[2];
    const float* W       = (const float*)d_in[3];
    const float* gamma   = (const float*)d_in[4];
    const float* beta    = (const float*)d_in[5];
    float* out = (float*)d_out;

    int N = in_sizes[1];

    k_zero<<<1, 64>>>();
    k_stats<<<(N + 63) / 64, 64>>>((const float4*)voxels, npp,
                                   (const float2*)centers, N);
    k_bn<<<1, 64>>>(W, gamma, beta, N);
    k_main<<<1184, 256>>>((const float4*)voxels, npp, (const float2*)centers,
                          W, out, N);
}